// round 11
// baseline (speedup 1.0000x reference)
#include <cuda_runtime.h>
#include <cuda_bf16.h>
#include <math.h>

// B=16, C=22, L=3000, D=64, D2=256, E=8, T=4, K=13
// Only output token n=0 matters -> only tokens n=0..6 (conv q=0..17, x[:, :, 0..40]).

__device__ float g_hln[16 * 448];        // LN'd tokens [b][n=0..6][d]   (n=0 = cls)
__device__ float g_tp[16 * 256];         // tokens_pre [b][o]
__device__ float g_tokT[256 * 16];       // transposed tokens [d][b]
__device__ float g_coef[16 * 16];        // per-b coef for 9 matrices (0 if unselected)
__device__ float g_ye[9 * 16 * 256];     // dense matrix outputs [m][b][f] (post-GELU)
__device__ int   g_cnt3;                 // last-block counters (self-resetting)
__device__ int   g_cntB;

__device__ __forceinline__ float gelu_exact(float x) {
    return 0.5f * x * (1.0f + erff(x * 0.70710678118654752f));
}

// ---------------------------------------------------------------------------
// K1: conv1d(stride2,pad6)+GELU+maxpool(3,3)+token LN (+cls LN in p==0 blocks)
// conv_w staged whole into dynamic smem (coalesced) - no transpose kernel.
// grid (6, 16) = (p, b), 192 threads = (qi 0..2) x (d 0..63)
// ---------------------------------------------------------------------------
__global__ void __launch_bounds__(192) k1_conv(
        const float* __restrict__ x,
        const float* __restrict__ cw,
        const float* __restrict__ cb,
        const float* __restrict__ cls,
        const float* __restrict__ tg,
        const float* __restrict__ tb) {
    extern __shared__ float cwsm[];   // 18304 floats = conv_w [64][286]
    __shared__ float xs[22][23];
    __shared__ float cv[3][64];
    int p = blockIdx.x, b = blockIdx.y, t = threadIdx.x;

    {   // stage conv_w: 4576 float4, coalesced
        const float4* src = (const float4*)cw;
        float4* dst = (float4*)cwsm;
        #pragma unroll 6
        for (int l = t; l < 4576; l += 192) dst[l] = __ldg(src + l);
    }
    int base = 6 * p - 6;
    for (int l = t; l < 22 * 23; l += 192) {
        int c = l / 23, j = l - c * 23;
        int xi = base + j;
        xs[c][j] = (xi >= 0) ? x[(b * 22 + c) * 3000 + xi] : 0.f;
    }
    __syncthreads();
    {
        int qi = t / 64, d = t & 63;
        float acc = __ldg(cb + d);
        const float* wp = cwsm + d * 286;
        #pragma unroll
        for (int c = 0; c < 22; c++) {
            #pragma unroll
            for (int k = 0; k < 13; k++)
                acc += wp[c * 13 + k] * xs[c][2 * qi + k];
        }
        cv[qi][d] = gelu_exact(acc);
    }
    __syncthreads();
    if (t < 32) {
        float v0 = fmaxf(fmaxf(cv[0][t], cv[1][t]), cv[2][t]);
        float v1 = fmaxf(fmaxf(cv[0][t + 32], cv[1][t + 32]), cv[2][t + 32]);
        float s = v0 + v1;
        #pragma unroll
        for (int off = 16; off; off >>= 1) s += __shfl_xor_sync(0xffffffffu, s, off);
        float mean = s * (1.f / 64.f);
        float d0 = v0 - mean, d1 = v1 - mean;
        float q = d0 * d0 + d1 * d1;
        #pragma unroll
        for (int off = 16; off; off >>= 1) q += __shfl_xor_sync(0xffffffffu, q, off);
        float rstd = rsqrtf(q * (1.f / 64.f) + 1e-5f);
        float* dst = g_hln + b * 448 + (p + 1) * 64;
        dst[t]      = d0 * rstd * __ldg(tg + t)      + __ldg(tb + t);
        dst[t + 32] = d1 * rstd * __ldg(tg + t + 32) + __ldg(tb + t + 32);
    } else if (p == 0 && t < 64) {
        int lane = t - 32;
        float v0 = __ldg(cls + lane), v1 = __ldg(cls + lane + 32);
        float s = v0 + v1;
        #pragma unroll
        for (int off = 16; off; off >>= 1) s += __shfl_xor_sync(0xffffffffu, s, off);
        float mean = s * (1.f / 64.f);
        float d0 = v0 - mean, d1 = v1 - mean;
        float q = d0 * d0 + d1 * d1;
        #pragma unroll
        for (int off = 16; off; off >>= 1) q += __shfl_xor_sync(0xffffffffu, q, off);
        float rstd = rsqrtf(q * (1.f / 64.f) + 1e-5f);
        float* dst = g_hln + b * 448;
        dst[lane]      = d0 * rstd * __ldg(tg + lane)      + __ldg(tb + lane);
        dst[lane + 32] = d1 * rstd * __ldg(tg + lane + 32) + __ldg(tb + lane + 32);
    }
}

// ---------------------------------------------------------------------------
// K3G: fold ds_conv into ds_comp_w, apply to tokens -> g_tp; LAST block also
// does the gate stage (LN+GELU+top-2 gating for all 16 b) in its tail.
// grid 256 (o), 1024 threads. W streamed float4 via 64KB dynamic smem.
// ---------------------------------------------------------------------------
__global__ void __launch_bounds__(1024) k3g(
        const float* __restrict__ W,
        const float* __restrict__ w1,
        const float* __restrict__ dcb,
        const float* __restrict__ dcompb,
        const int* __restrict__ task_ids,
        const float* __restrict__ task_embed,
        const float* __restrict__ ds_g,
        const float* __restrict__ ds_b,
        const float* __restrict__ gate_w,
        const float* __restrict__ gate_b) {
    extern __shared__ float ws[];     // 16384 floats = [c][d] tile for this o
    __shared__ float w1s[256 * 8];    // [c][k]; k=7 slot holds dcb[c]
    __shared__ float up[16][8][64];   // [cgrp][k][d] partials
    __shared__ float red[32][8];      // [warp][b-in-half]
    __shared__ float ttok[1024];      // tail: 4 groups x 256 tokens
    __shared__ float redA[4][8];
    __shared__ float redB[4][8];
    __shared__ float gshs[4][8];
    __shared__ int lastf;
    int o = blockIdx.x, t = threadIdx.x;
    int w = t >> 5, lane = t & 31;

    for (int l = t; l < 2048; l += 1024) {
        int c = l >> 3, k = l & 7;
        w1s[l] = (k < 7) ? __ldg(w1 + c * 13 + 6 + k) : __ldg(dcb + c);
    }
    {   // W tile, coalesced float4, MLP=4
        const float4* src = (const float4*)(W + (long)o * 16384);
        float4 v[4];
        #pragma unroll
        for (int i = 0; i < 4; i++) v[i] = __ldg(src + t + i * 1024);
        #pragma unroll
        for (int i = 0; i < 4; i++) ((float4*)ws)[t + i * 1024] = v[i];
    }
    __syncthreads();

    // phase A: cg covers 16 c's; fold taps
    {
        int cg = t >> 6, d = t & 63, c0 = cg * 16;
        float u[8] = {0.f, 0.f, 0.f, 0.f, 0.f, 0.f, 0.f, 0.f};
        #pragma unroll
        for (int j = 0; j < 16; j++) {
            float s = ws[(c0 + j) * 64 + d];
            const float4* wr = (const float4*)(w1s + (c0 + j) * 8);
            float4 wa = wr[0], wb = wr[1];
            u[0] += s * wa.x; u[1] += s * wa.y; u[2] += s * wa.z; u[3] += s * wa.w;
            u[4] += s * wb.x; u[5] += s * wb.y; u[6] += s * wb.z; u[7] += s * wb.w;
        }
        #pragma unroll
        for (int k = 0; k < 8; k++) up[cg][k][d] = u[k];
    }
    __syncthreads();

    // phase B: group g2 = (bh, kk); dot with hln for 8 b's
    {
        int g2 = t >> 6, d = t & 63;
        int kk = g2 & 7, bh = g2 >> 3;
        float uf = 0.f;
        #pragma unroll
        for (int g = 0; g < 16; g++) uf += up[g][kk][d];

        float tpv[8];
        if (kk < 7) {
            float hv[8];
            const float* hp = g_hln + kk * 64 + d + bh * 8 * 448;
            #pragma unroll
            for (int i = 0; i < 8; i++) hv[i] = __ldg(hp + i * 448);
            #pragma unroll
            for (int i = 0; i < 8; i++) tpv[i] = uf * hv[i];
        } else {
            #pragma unroll
            for (int i = 0; i < 8; i++) tpv[i] = uf;
        }
        #pragma unroll
        for (int i = 0; i < 8; i++) {
            #pragma unroll
            for (int off = 16; off; off >>= 1)
                tpv[i] += __shfl_xor_sync(0xffffffffu, tpv[i], off);
        }
        if (lane < 8) red[w][lane] = tpv[lane];
    }
    __syncthreads();
    if (t < 16) {
        int b = t, base = (b >> 3) * 16;
        float s = 0.f;
        #pragma unroll
        for (int j = 0; j < 16; j++) s += red[base + j][b & 7];
        g_tp[b * 256 + o] = s + __ldg(dcompb + o);
    }

    // -------- last-block gate tail --------
    __threadfence();
    if (t == 0) lastf = (atomicAdd(&g_cnt3, 1) == 255) ? 1 : 0;
    __syncthreads();
    if (!lastf) return;
    __threadfence();

    int grp = t >> 8, tt = t & 255;
    int wg = tt >> 5;
    #pragma unroll 1
    for (int i = 0; i < 4; i++) {
        int b = grp * 4 + i;
        float tp = g_tp[b * 256 + tt];
        float s = tp;
        #pragma unroll
        for (int off = 16; off; off >>= 1) s += __shfl_xor_sync(0xffffffffu, s, off);
        if (lane == 0) redA[grp][wg] = s;
        __syncthreads();
        float mean = 0.f;
        #pragma unroll
        for (int j = 0; j < 8; j++) mean += redA[grp][j];
        mean *= (1.f / 256.f);
        float dv = tp - mean;
        float q = dv * dv;
        #pragma unroll
        for (int off = 16; off; off >>= 1) q += __shfl_xor_sync(0xffffffffu, q, off);
        if (lane == 0) redB[grp][wg] = q;
        __syncthreads();
        float var = 0.f;
        #pragma unroll
        for (int j = 0; j < 8; j++) var += redB[grp][j];
        float rstd = rsqrtf(var * (1.f / 256.f) + 1e-5f);
        float tv = gelu_exact(dv * rstd * __ldg(ds_g + tt) + __ldg(ds_b + tt));
        ttok[grp * 256 + tt] = tv;
        g_tokT[tt * 16 + b] = tv;
        __syncthreads();

        // gating: warp wg (0..7 per group) computes logit e = wg for this b
        {
            const float* te = task_embed + __ldg(task_ids + b) * 256;
            float sg = 0.f;
            #pragma unroll
            for (int i2 = 0; i2 < 8; i2++) {
                int oo = lane + i2 * 32;
                sg += ttok[grp * 256 + oo] * __ldg(gate_w + oo * 8 + wg)
                    + __ldg(te + oo) * __ldg(gate_w + (256 + oo) * 8 + wg);
            }
            #pragma unroll
            for (int off = 16; off; off >>= 1) sg += __shfl_xor_sync(0xffffffffu, sg, off);
            if (lane == 0) gshs[grp][wg] = sg + __ldg(gate_b + wg);
        }
        __syncthreads();
        if (tt == 0) {
            float v1 = -1e30f; int e1 = 0;
            #pragma unroll
            for (int e = 0; e < 8; e++) if (gshs[grp][e] > v1) { v1 = gshs[grp][e]; e1 = e; }
            float v2 = -1e30f; int e2 = 0;
            #pragma unroll
            for (int e = 0; e < 8; e++) if (e != e1 && gshs[grp][e] > v2) { v2 = gshs[grp][e]; e2 = e; }
            float g1 = 1.f / (1.f + expf(v2 - v1));
            float c[9];
            #pragma unroll
            for (int m = 0; m < 9; m++) c[m] = 0.f;
            c[e1] = g1; c[e2] = 1.f - g1; c[8] = 1.f - g1;  // omega = 1 - max gate
            #pragma unroll
            for (int m = 0; m < 9; m++) g_coef[b * 16 + m] = c[m];
        }
        __syncthreads();
    }
    if (t == 0) g_cnt3 = 0;   // reset for next graph replay
}

// ---------------------------------------------------------------------------
// KBO: dense matrices (8 experts + universal) for ALL b, weights read ONCE;
// LAST block does the gated combine + final LN + output write in its tail.
// grid (9, 16) = (matrix m, f-slice of 16 f). 256 threads.
// ---------------------------------------------------------------------------
__global__ void __launch_bounds__(256) kBo(
        const float* __restrict__ exp_w,
        const float* __restrict__ exp_b,
        const float* __restrict__ uni_w,
        const float* __restrict__ uni_b,
        const float* __restrict__ out_g,
        const float* __restrict__ out_b,
        float* __restrict__ out) {
    __shared__ float wsm[4096];   // [d][16f] slice; reused as psm after compute
    __shared__ float tsm[4096];   // tokT [d][16b]
    __shared__ int lastf;
    int m = blockIdx.x, fs = blockIdx.y, t = threadIdx.x;
    int f0 = fs * 16;
    const float* Wb = (m < 8) ? exp_w + (long)m * 65536 : uni_w;

    {   // load W slice: q = t&3 (f-quad), dbase = t>>2; 4 rows each
        int q = t & 3, dbase = t >> 2;
        float4 v[4];
        #pragma unroll
        for (int i = 0; i < 4; i++) {
            int d = dbase + i * 64;
            v[i] = __ldg((const float4*)(Wb + d * 256 + f0) + q);
        }
        #pragma unroll
        for (int i = 0; i < 4; i++)
            ((float4*)wsm)[(dbase + i * 64) * 4 + q] = v[i];
    }
    {   // load tokT (contiguous)
        float4 v[4];
        #pragma unroll
        for (int i = 0; i < 4; i++)
            v[i] = __ldg((const float4*)g_tokT + t + i * 256);
        #pragma unroll
        for (int i = 0; i < 4; i++)
            ((float4*)tsm)[t + i * 256] = v[i];
    }
    __syncthreads();

    // compute: thread = (dsl = t>>4 covering 16 d, bq = (t>>2)&3, fq = t&3)
    int dsl = t >> 4, bq = (t >> 2) & 3, fq = t & 3;
    float4 acc[4];
    #pragma unroll
    for (int i = 0; i < 4; i++) acc[i] = make_float4(0.f, 0.f, 0.f, 0.f);
    const float4* wsm4 = (const float4*)wsm;
    const float4* tsm4 = (const float4*)tsm;
    #pragma unroll
    for (int j = 0; j < 16; j++) {
        int d = dsl * 16 + j;
        float4 wq = wsm4[d * 4 + fq];
        float4 tq = tsm4[d * 4 + bq];
        acc[0].x += tq.x * wq.x; acc[0].y += tq.x * wq.y; acc[0].z += tq.x * wq.z; acc[0].w += tq.x * wq.w;
        acc[1].x += tq.y * wq.x; acc[1].y += tq.y * wq.y; acc[1].z += tq.y * wq.z; acc[1].w += tq.y * wq.w;
        acc[2].x += tq.z * wq.x; acc[2].y += tq.z * wq.y; acc[2].z += tq.z * wq.z; acc[2].w += tq.z * wq.w;
        acc[3].x += tq.w * wq.x; acc[3].y += tq.w * wq.y; acc[3].z += tq.w * wq.z; acc[3].w += tq.w * wq.w;
    }
    __syncthreads();
    float* psm = wsm;
    #pragma unroll
    for (int bi = 0; bi < 4; bi++) {
        int b = bq * 4 + bi;
        ((float4*)psm)[dsl * 64 + b * 4 + fq] = acc[bi];
    }
    __syncthreads();

    {   // reduce + bias + gelu -> g_ye
        int b = t >> 4, fi = t & 15;
        float s = 0.f;
        #pragma unroll
        for (int ds = 0; ds < 16; ds++) s += psm[ds * 256 + b * 16 + fi];
        float bias = (m < 8) ? __ldg(exp_b + m * 256 + f0 + fi) : __ldg(uni_b + f0 + fi);
        g_ye[(m * 16 + b) * 256 + f0 + fi] = gelu_exact(s + bias);
    }

    // -------- last-block output tail --------
    __threadfence();
    if (t == 0) lastf = (atomicAdd(&g_cntB, 1) == 143) ? 1 : 0;
    __syncthreads();
    if (!lastf) return;
    __threadfence();

    {
        int b = t >> 4, j = t & 15;
        float coef[9];
        #pragma unroll
        for (int mm = 0; mm < 9; mm++) coef[mm] = g_coef[b * 16 + mm];
        float val[16];
        #pragma unroll
        for (int i = 0; i < 16; i++) val[i] = 0.f;
        #pragma unroll
        for (int mm = 0; mm < 9; mm++) {
            float yv[16];
            #pragma unroll
            for (int i = 0; i < 16; i++)
                yv[i] = g_ye[(mm * 16 + b) * 256 + i * 16 + j];
            #pragma unroll
            for (int i = 0; i < 16; i++) val[i] += coef[mm] * yv[i];
        }
        float s = 0.f;
        #pragma unroll
        for (int i = 0; i < 16; i++) s += val[i];
        #pragma unroll
        for (int off = 8; off; off >>= 1) s += __shfl_xor_sync(0xffffffffu, s, off);
        float mean = s * (1.f / 256.f);
        float q = 0.f;
        #pragma unroll
        for (int i = 0; i < 16; i++) { float dv = val[i] - mean; q += dv * dv; }
        #pragma unroll
        for (int off = 8; off; off >>= 1) q += __shfl_xor_sync(0xffffffffu, q, off);
        float rstd = rsqrtf(q * (1.f / 256.f) + 1e-5f);
        #pragma unroll
        for (int i = 0; i < 16; i++) {
            int f = i * 16 + j;
            out[b * 256 + f] = (val[i] - mean) * rstd * __ldg(out_g + f) + __ldg(out_b + f);
        }
    }
    if (t == 0) g_cntB = 0;   // reset for next graph replay
}

// ---------------------------------------------------------------------------
extern "C" void kernel_launch(void* const* d_in, const int* in_sizes, int n_in,
                              void* d_out, int out_size) {
    const float* x_stream   = (const float*)d_in[0];
    const int*   task_ids   = (const int*)  d_in[1];
    const float* conv_w     = (const float*)d_in[2];
    const float* conv_b     = (const float*)d_in[3];
    const float* cls_token  = (const float*)d_in[4];
    const float* tok_g      = (const float*)d_in[5];
    const float* tok_b      = (const float*)d_in[6];
    const float* ds_conv_w  = (const float*)d_in[7];
    const float* ds_conv_b  = (const float*)d_in[8];
    const float* ds_comp_w  = (const float*)d_in[9];
    const float* ds_comp_b  = (const float*)d_in[10];
    const float* ds_g       = (const float*)d_in[11];
    const float* ds_b       = (const float*)d_in[12];
    const float* task_embed = (const float*)d_in[13];
    const float* gate_w     = (const float*)d_in[14];
    const float* gate_b     = (const float*)d_in[15];
    const float* exp_w      = (const float*)d_in[16];
    const float* exp_b      = (const float*)d_in[17];
    const float* uni_w      = (const float*)d_in[18];
    const float* uni_b      = (const float*)d_in[19];
    const float* out_g      = (const float*)d_in[20];
    const float* out_b      = (const float*)d_in[21];
    float* out = (float*)d_out;

    cudaFuncSetAttribute(k1_conv, cudaFuncAttributeMaxDynamicSharedMemorySize,
                         18304 * sizeof(float));
    cudaFuncSetAttribute(k3g, cudaFuncAttributeMaxDynamicSharedMemorySize,
                         16384 * sizeof(float));

    k1_conv<<<dim3(6, 16), 192, 18304 * sizeof(float)>>>(
        x_stream, conv_w, conv_b, cls_token, tok_g, tok_b);
    k3g<<<256, 1024, 16384 * sizeof(float)>>>(
        ds_comp_w, ds_conv_w, ds_conv_b, ds_comp_b,
        task_ids, task_embed, ds_g, ds_b, gate_w, gate_b);
    kBo<<<dim3(9, 16), 256>>>(exp_w, exp_b, uni_w, uni_b, out_g, out_b, out);
}

// round 15
// speedup vs baseline: 1.7544x; 1.7544x over previous
#include <cuda_runtime.h>
#include <cuda_bf16.h>
#include <math.h>

// B=16, C=22, L=3000, D=64, D2=256, E=8, T=4, K=13
// Only output token n=0 matters -> tokens n=0..6 (conv q=0..17, x[:, :, 0..40]).
// Single persistent kernel, 256 blocks x 512 threads, software grid barriers.

#define GRID 256

__device__ float g_cwT[286 * 64];        // transposed conv_w [(c*13+k)][d]
__device__ float g_hln[16 * 448];        // LN'd tokens [b][n=0..6][d]
__device__ float g_tp[16 * 256];         // tokens_pre [b][o]
__device__ float g_y[16 * 3 * 256];      // gated GEMV outputs [b][g][f]
__device__ int   g_arrive;               // monotonic barrier counter
__device__ int   g_depart;               // departure counter (resets state)

__device__ __forceinline__ float gelu_exact(float x) {
    return 0.5f * x * (1.0f + erff(x * 0.70710678118654752f));
}

// grid barrier k (k = 1,2,3,...): pass when total arrivals >= k*GRID
__device__ __forceinline__ void gbar(int k) {
    __syncthreads();
    if (threadIdx.x == 0) {
        __threadfence();
        atomicAdd(&g_arrive, 1);
        while (*((volatile int*)&g_arrive) < k * GRID) __nanosleep(64);
        __threadfence();
    }
    __syncthreads();
}

__device__ __forceinline__ float bsum512(float v, float* red) {
    #pragma unroll
    for (int off = 16; off; off >>= 1) v += __shfl_xor_sync(0xffffffffu, v, off);
    int w = threadIdx.x >> 5;
    if ((threadIdx.x & 31) == 0) red[w] = v;
    __syncthreads();
    if (threadIdx.x < 32) {
        float xv = (threadIdx.x < 16) ? red[threadIdx.x] : 0.f;
        #pragma unroll
        for (int off = 8; off; off >>= 1) xv += __shfl_xor_sync(0xffffffffu, xv, off);
        if (threadIdx.x == 0) red[0] = xv;
    }
    __syncthreads();
    float r = red[0];
    __syncthreads();
    return r;
}

__global__ void __launch_bounds__(512, 2) mega(
        const float* __restrict__ x,
        const int*   __restrict__ task_ids,
        const float* __restrict__ cw,
        const float* __restrict__ cb,
        const float* __restrict__ cls,
        const float* __restrict__ tg,
        const float* __restrict__ tb,
        const float* __restrict__ w1,
        const float* __restrict__ dcb,
        const float* __restrict__ W,
        const float* __restrict__ dcompb,
        const float* __restrict__ ds_g,
        const float* __restrict__ ds_b,
        const float* __restrict__ task_embed,
        const float* __restrict__ gate_w,
        const float* __restrict__ gate_b,
        const float* __restrict__ exp_w,
        const float* __restrict__ exp_b,
        const float* __restrict__ uni_w,
        const float* __restrict__ uni_b,
        const float* __restrict__ out_g,
        const float* __restrict__ out_b,
        float* __restrict__ out)
{
    int blk = blockIdx.x, t = threadIdx.x;
    int w = t >> 5, lane = t & 31;

    // 16B-aligned shared arrays (s_w1 and s_part are accessed via float4*)
    __shared__ __align__(16) float s_w1[2048];      // [c][k]; k=7 slot = dcb[c]
    __shared__ __align__(16) float s_part[8][256];
    __shared__ __align__(16) float s_up[8][8][64];  // [cgrp][k][d]
    __shared__ __align__(16) float s_tok[256];
    __shared__ float s_xs[22][23];
    __shared__ float s_cv[3][64];
    __shared__ float s_red16[16][16];
    __shared__ float s_red[32];
    __shared__ float s_gsh[8];
    __shared__ int   s_esel;
    __shared__ float s_coef;

    // ---- P1: transpose conv_w [64][286] -> g_cwT [(c*13+k)][64] ----
    {
        int idx = blk * 512 + t;
        if (idx < 18304) {
            int d = idx / 286, ck = idx - d * 286;
            g_cwT[ck * 64 + d] = __ldg(cw + idx);
        }
    }
    gbar(1);

    // ---- P2: conv1d(stride2,pad6)+GELU+maxpool(3,3)+token LN (+cls LN) ----
    if (blk < 96) {
        int p = blk % 6, b = blk / 6;
        int base = 6 * p - 6;
        for (int l = t; l < 506; l += 512) {
            int c = l / 23, j = l - c * 23;
            int xi = base + j;
            s_xs[c][j] = (xi >= 0) ? x[(b * 22 + c) * 3000 + xi] : 0.f;
        }
        __syncthreads();
        if (t < 192) {
            int qi = t / 64, d = t & 63;
            float acc = __ldg(cb + d);
            #pragma unroll
            for (int c = 0; c < 22; c += 2) {
                float wv[26];
                #pragma unroll
                for (int k = 0; k < 26; k++)
                    wv[k] = __ldg(g_cwT + (c * 13 + k) * 64 + d);
                #pragma unroll
                for (int k = 0; k < 13; k++) acc += wv[k] * s_xs[c][2 * qi + k];
                #pragma unroll
                for (int k = 0; k < 13; k++) acc += wv[13 + k] * s_xs[c + 1][2 * qi + k];
            }
            s_cv[qi][d] = gelu_exact(acc);
        }
        __syncthreads();
        if (t < 32) {
            float v0 = fmaxf(fmaxf(s_cv[0][t], s_cv[1][t]), s_cv[2][t]);
            float v1 = fmaxf(fmaxf(s_cv[0][t + 32], s_cv[1][t + 32]), s_cv[2][t + 32]);
            float s = v0 + v1;
            #pragma unroll
            for (int off = 16; off; off >>= 1) s += __shfl_xor_sync(0xffffffffu, s, off);
            float mean = s * (1.f / 64.f);
            float d0 = v0 - mean, d1 = v1 - mean;
            float q = d0 * d0 + d1 * d1;
            #pragma unroll
            for (int off = 16; off; off >>= 1) q += __shfl_xor_sync(0xffffffffu, q, off);
            float rstd = rsqrtf(q * (1.f / 64.f) + 1e-5f);
            float* dst = g_hln + b * 448 + (p + 1) * 64;
            dst[t]      = d0 * rstd * __ldg(tg + t)      + __ldg(tb + t);
            dst[t + 32] = d1 * rstd * __ldg(tg + t + 32) + __ldg(tb + t + 32);
        } else if (p == 0 && t < 64) {
            int l2 = t - 32;
            float v0 = __ldg(cls + l2), v1 = __ldg(cls + l2 + 32);
            float s = v0 + v1;
            #pragma unroll
            for (int off = 16; off; off >>= 1) s += __shfl_xor_sync(0xffffffffu, s, off);
            float mean = s * (1.f / 64.f);
            float d0 = v0 - mean, d1 = v1 - mean;
            float q = d0 * d0 + d1 * d1;
            #pragma unroll
            for (int off = 16; off; off >>= 1) q += __shfl_xor_sync(0xffffffffu, q, off);
            float rstd = rsqrtf(q * (1.f / 64.f) + 1e-5f);
            float* dst = g_hln + b * 448;
            dst[l2]      = d0 * rstd * __ldg(tg + l2)      + __ldg(tb + l2);
            dst[l2 + 32] = d1 * rstd * __ldg(tg + l2 + 32) + __ldg(tb + l2 + 32);
        }
    }
    gbar(2);

    // ---- P3: fold ds_conv into ds_comp_w and apply -> g_tp. o = blk ----
    {
        int o = blk;
        for (int l = t; l < 2048; l += 512) {
            int c = l >> 3, k = l & 7;
            s_w1[l] = (k < 7) ? __ldg(w1 + c * 13 + 6 + k) : __ldg(dcb + c);
        }
        __syncthreads();
        {
            int cg = t >> 6, d = t & 63, c0 = cg * 32;
            float u[8] = {0.f, 0.f, 0.f, 0.f, 0.f, 0.f, 0.f, 0.f};
            const float* Wo = W + (long)o * 16384 + (long)c0 * 64 + d;
            #pragma unroll
            for (int half = 0; half < 2; half++) {
                float wv[16];
                #pragma unroll
                for (int j = 0; j < 16; j++)
                    wv[j] = __ldg(Wo + (half * 16 + j) * 64);
                #pragma unroll
                for (int j = 0; j < 16; j++) {
                    const float4* wr = (const float4*)(s_w1 + (c0 + half * 16 + j) * 8);
                    float4 wa = wr[0], wb = wr[1];
                    u[0] += wv[j] * wa.x; u[1] += wv[j] * wa.y;
                    u[2] += wv[j] * wa.z; u[3] += wv[j] * wa.w;
                    u[4] += wv[j] * wb.x; u[5] += wv[j] * wb.y;
                    u[6] += wv[j] * wb.z; u[7] += wv[j] * wb.w;
                }
            }
            #pragma unroll
            for (int k = 0; k < 8; k++) s_up[cg][k][d] = u[k];
        }
        __syncthreads();
        {
            int kk = t >> 6, d = t & 63;
            float uf = 0.f;
            #pragma unroll
            for (int g = 0; g < 8; g++) uf += s_up[g][kk][d];
            float tpv[16];
            if (kk < 7) {
                const float* hp = g_hln + kk * 64 + d;
                float hv[16];
                #pragma unroll
                for (int b = 0; b < 16; b++) hv[b] = __ldg(hp + b * 448);
                #pragma unroll
                for (int b = 0; b < 16; b++) tpv[b] = uf * hv[b];
            } else {
                #pragma unroll
                for (int b = 0; b < 16; b++) tpv[b] = uf;
            }
            #pragma unroll
            for (int b = 0; b < 16; b++) {
                #pragma unroll
                for (int off = 16; off; off >>= 1)
                    tpv[b] += __shfl_xor_sync(0xffffffffu, tpv[b], off);
            }
            if (lane < 16) s_red16[w][lane] = tpv[lane];
        }
        __syncthreads();
        if (t < 16) {
            float s = 0.f;
            #pragma unroll
            for (int w2 = 0; w2 < 16; w2++) s += s_red16[w2][t];
            g_tp[t * 256 + o] = s + __ldg(dcompb + o);
        }
    }
    gbar(3);

    // ---- P4: gate (recomputed per block) + expert/universal GEMV ----
    // blk < 48: g = blk>>4 (0,1 = experts; 2 = universal), b = blk&15
    if (blk < 48) {
        int g = blk >> 4, b = blk & 15;
        float tp = (t < 256) ? g_tp[b * 256 + t] : 0.f;
        float mean = bsum512(tp, s_red) * (1.f / 256.f);
        float dv = tp - mean;
        float var = bsum512((t < 256) ? dv * dv : 0.f, s_red) * (1.f / 256.f);
        float rstd = rsqrtf(var + 1e-5f);
        if (t < 256) s_tok[t] = gelu_exact(dv * rstd * __ldg(ds_g + t) + __ldg(ds_b + t));
        __syncthreads();
        if (t < 256) {   // warps 0..7: logit per expert
            const float* te = task_embed + __ldg(task_ids + b) * 256;
            float s = 0.f;
            #pragma unroll
            for (int i = 0; i < 8; i++) {
                int o = lane + i * 32;
                s += s_tok[o] * __ldg(gate_w + o * 8 + w)
                   + __ldg(te + o) * __ldg(gate_w + (256 + o) * 8 + w);
            }
            #pragma unroll
            for (int off = 16; off; off >>= 1) s += __shfl_xor_sync(0xffffffffu, s, off);
            if (lane == 0) s_gsh[w] = s + __ldg(gate_b + w);
        }
        __syncthreads();
        if (t == 0) {
            float v1 = -1e30f; int e1 = 0;
            #pragma unroll
            for (int e = 0; e < 8; e++) if (s_gsh[e] > v1) { v1 = s_gsh[e]; e1 = e; }
            float v2 = -1e30f; int e2 = 0;
            #pragma unroll
            for (int e = 0; e < 8; e++) if (e != e1 && s_gsh[e] > v2) { v2 = s_gsh[e]; e2 = e; }
            float g1 = 1.f / (1.f + expf(v2 - v1));
            if (g == 0)      { s_esel = e1; s_coef = g1; }
            else if (g == 1) { s_esel = e2; s_coef = 1.f - g1; }
            else             { s_esel = 8;  s_coef = 1.f - g1; }  // omega = 1 - max gate
        }
        __syncthreads();
        const float* Wb = (s_esel < 8) ? exp_w + (long)s_esel * 65536 : uni_w;
        const float* Bb = (s_esel < 8) ? exp_b + s_esel * 256 : uni_b;
        int ds = t >> 6, f4 = (t & 63) * 4;
        int d0 = ds * 32;
        float4 acc = make_float4(0.f, 0.f, 0.f, 0.f);
        #pragma unroll
        for (int blk2 = 0; blk2 < 4; blk2++) {
            float4 w4[8];
            #pragma unroll
            for (int j = 0; j < 8; j++)
                w4[j] = __ldg((const float4*)(Wb + (d0 + blk2 * 8 + j) * 256 + f4));
            #pragma unroll
            for (int j = 0; j < 8; j++) {
                float tv = s_tok[d0 + blk2 * 8 + j];
                acc.x += tv * w4[j].x; acc.y += tv * w4[j].y;
                acc.z += tv * w4[j].z; acc.w += tv * w4[j].w;
            }
        }
        *(float4*)(&s_part[ds][f4]) = acc;
        __syncthreads();
        if (t < 256) {
            float s = 0.f;
            #pragma unroll
            for (int p = 0; p < 8; p++) s += s_part[p][t];
            g_y[(b * 3 + g) * 256 + t] = s_coef * gelu_exact(s + __ldg(Bb + t));
        }
    }
    gbar(4);

    // ---- P5: combine + final LN -> out ----
    if (blk < 16) {
        int b = blk;
        float val = 0.f;
        if (t < 256) {
            const float* y = g_y + b * 3 * 256;
            val = y[t] + y[256 + t] + y[512 + t];
        }
        float m = bsum512(val, s_red) * (1.f / 256.f);
        float dv = val - m;
        float v = bsum512((t < 256) ? dv * dv : 0.f, s_red) * (1.f / 256.f);
        float rs = rsqrtf(v + 1e-5f);
        if (t < 256) out[b * 256 + t] = dv * rs * __ldg(out_g + t) + __ldg(out_b + t);
    }

    // ---- departure: last block resets barrier state for next graph replay ----
    __syncthreads();
    if (t == 0) {
        __threadfence();
        if (atomicAdd(&g_depart, 1) == GRID - 1) {
            g_arrive = 0;
            g_depart = 0;
            __threadfence();
        }
    }
}

// ---------------------------------------------------------------------------
extern "C" void kernel_launch(void* const* d_in, const int* in_sizes, int n_in,
                              void* d_out, int out_size) {
    const float* x_stream   = (const float*)d_in[0];
    const int*   task_ids   = (const int*)  d_in[1];
    const float* conv_w     = (const float*)d_in[2];
    const float* conv_b     = (const float*)d_in[3];
    const float* cls_token  = (const float*)d_in[4];
    const float* tok_g      = (const float*)d_in[5];
    const float* tok_b      = (const float*)d_in[6];
    const float* ds_conv_w  = (const float*)d_in[7];
    const float* ds_conv_b  = (const float*)d_in[8];
    const float* ds_comp_w  = (const float*)d_in[9];
    const float* ds_comp_b  = (const float*)d_in[10];
    const float* ds_g       = (const float*)d_in[11];
    const float* ds_b       = (const float*)d_in[12];
    const float* task_embed = (const float*)d_in[13];
    const float* gate_w     = (const float*)d_in[14];
    const float* gate_b     = (const float*)d_in[15];
    const float* exp_w      = (const float*)d_in[16];
    const float* exp_b      = (const float*)d_in[17];
    const float* uni_w      = (const float*)d_in[18];
    const float* uni_b      = (const float*)d_in[19];
    const float* out_g      = (const float*)d_in[20];
    const float* out_b      = (const float*)d_in[21];
    float* out = (float*)d_out;

    mega<<<GRID, 512>>>(x_stream, task_ids, conv_w, conv_b, cls_token,
                        tok_g, tok_b, ds_conv_w, ds_conv_b, ds_comp_w,
                        ds_comp_b, ds_g, ds_b, task_embed, gate_w, gate_b,
                        exp_w, exp_b, uni_w, uni_b, out_g, out_b, out);
}